// round 3
// baseline (speedup 1.0000x reference)
#include <cuda_runtime.h>
#include <cstdint>

#define RR 8192
#define NX 32
#define NM 64
#define WST 97            // 32 (M) + 32 (-ap) + 1 (w) + 32 (I)
#define FW_S 32
#define FW_W 96
#define FW_BLOCKS (RR/FW_S)   // 256
#define BW_S 64
#define BW_W 96
#define BW_BLOCKS (RR/BW_S)   // 128
#define NT 512

// Scratch: forward pass products consumed by backward pass.
// g_linvT[r][i][j] = (L_r^{-1})[j][i]  (transposed L-inverse, row-major)
// g_offT [r][k][i] = off_r[i][k]       (i.e. Y = L^{-1}(-ap), row-major)
__device__ float g_linvT[RR*NX*NX];
__device__ float g_offT [RR*NX*NX];
__device__ float g_u    [RR*NX];

// ---------------------------------------------------------------------------
// Forward: chunked scan with warm-up. Augmented LDL^T elimination fuses
// Cholesky + solve(L, -ap) + solve(L, w) + explicit L^{-1} in one sweep.
// ---------------------------------------------------------------------------
__global__ __launch_bounds__(NT) void fwd_kernel(
    const float* __restrict__ hess, const float* __restrict__ grads,
    const float* __restrict__ Amat, const float* __restrict__ Ptp,
    const float* __restrict__ Pinit)
{
    __shared__ float W[NX*WST];
    __shared__ float pred[NX*33];
    __shared__ float offT[NX*33];
    __shared__ float ap_s[NX*33];
    __shared__ float apat_s[NX*33];
    __shared__ float P_s[NX*33];
    __shared__ float A_s[NX*33];
    __shared__ float u_s[NX];
    __shared__ float rstd_s[NX];

    const int tid = threadIdx.x;
    const int b   = blockIdx.x;
    int r0 = b*FW_S - FW_W; if (r0 < 0) r0 = 0;
    const int rend  = (b+1)*FW_S;
    const int rmain = b*FW_S;
    const int nsteps = rend - r0;
    const bool exact = (r0 == 0);   // exact init chain (no approximation)

    // Load constants, init carry (pred = Pinit exact, else guess Ptp; off=0, u=0)
    for (int idx = tid; idx < NX*NX; idx += NT) {
        int i = idx >> 5, j = idx & 31;
        A_s [i*33+j] = Amat[idx];
        P_s [i*33+j] = Ptp[idx];
        pred[i*33+j] = exact ? Pinit[idx] : Ptp[idx];
        offT[i*33+j] = 0.f;
    }
    if (tid < NX) u_s[tid] = 0.f;
    __syncthreads();
    // ap = A @ Ptp
    for (int idx = tid; idx < NX*NX; idx += NT) {
        int i = idx >> 5, j = idx & 31;
        float s = 0.f;
        #pragma unroll
        for (int k = 0; k < NX; k++) s += A_s[i*33+k]*P_s[k*33+j];
        ap_s[i*33+j] = s;
    }
    __syncthreads();
    // apat = ap @ A^T
    for (int idx = tid; idx < NX*NX; idx += NT) {
        int i = idx >> 5, j = idx & 31;
        float s = 0.f;
        #pragma unroll
        for (int k = 0; k < NX; k++) s += ap_s[i*33+k]*A_s[j*33+k];
        apat_s[i*33+j] = s;
    }
    __syncthreads();

    const int i0 = tid >> 5;   // 0..15
    const int j0 = tid & 31;

    // register prefetch of hess / grad for first step
    float h0 = hess[(size_t)r0*1024 + tid];
    float h1 = hess[(size_t)r0*1024 + 512 + tid];
    float gpre = (tid < NX) ? grads[r0*NX + tid] : 0.f;

    for (int step = 0; step < nsteps; step++) {
        const int r = r0 + step;
        const float mfac = (r == RR-1) ? 0.f : 1.f;

        // ---- build augmented W = [pred+hess+m*apat | -ap | w | I] ----
        W[i0*WST + j0]          = pred[i0*33+j0]      + h0 + mfac*apat_s[i0*33+j0];
        W[(i0+16)*WST + j0]     = pred[(i0+16)*33+j0] + h1 + mfac*apat_s[(i0+16)*33+j0];
        W[i0*WST + 32 + j0]     = -ap_s[i0*33+j0];
        W[(i0+16)*WST + 32 + j0]= -ap_s[(i0+16)*33+j0];
        W[i0*WST + 65 + j0]     = (i0 == j0) ? 1.f : 0.f;
        W[(i0+16)*WST + 65 + j0]= ((i0+16) == j0) ? 1.f : 0.f;
        if (tid < NX) {   // w = grad - u @ off^T   (uses previous step's off, u)
            float wv = gpre;
            #pragma unroll
            for (int k = 0; k < NX; k++) wv -= u_s[k]*offT[k*33 + tid];
            W[tid*WST + 64] = wv;
        }
        // prefetch next step's hess/grad (LDG latency hidden under elimination)
        if (step + 1 < nsteps) {
            h0 = hess[(size_t)(r+1)*1024 + tid];
            h1 = hess[(size_t)(r+1)*1024 + 512 + tid];
            if (tid < NX) gpre = grads[(r+1)*NX + tid];
        }
        __syncthreads();

        // ---- LDL^T elimination, one sync per pivot ----
        const int irow  = tid >> 4;   // 0..31 (row group)
        const int clane = tid & 15;   // 16 lanes across columns
        for (int k = 0; k < NX; k++) {
            const float inv_d = __frcp_rn(W[k*WST + k]);
            const int i = k + 1 + irow;
            if (i < NX) {
                const float lik = W[i*WST + k] * inv_d;
                for (int c = k + 1 + clane; c < WST; c += 16)
                    W[i*WST + c] -= lik * W[k*WST + c];
            }
            __syncthreads();
        }
        if (tid < NX) rstd_s[tid] = __frsqrt_rn(W[tid*WST + tid]);
        __syncthreads();

        const bool mainrow = (r >= rmain);
        const size_t rbase = (size_t)r * (NX*NX);

        // off^T rows (Y = L^{-1}(-ap)): offT[k][i] = W[k][32+i] * rstd[k]
        #pragma unroll
        for (int t = 0; t < 2; t++) {
            const int k = i0 + 16*t;
            const float ov = W[k*WST + 32 + j0] * rstd_s[k];
            offT[k*33 + j0] = ov;
            if (mainrow) g_offT[rbase + k*NX + j0] = ov;
        }
        // L^{-1} transposed store: g_linvT[r][c][k] = Linv[k][c]
        if (mainrow) {
            #pragma unroll
            for (int t = 0; t < 2; t++) {
                const int c = i0 + 16*t;    // Linv column
                const int k = j0;           // Linv row (lane: stride-97 smem, coalesced STG)
                g_linvT[rbase + c*NX + k] = W[k*WST + 65 + c] * rstd_s[k];
            }
        }
        // u' = (L^{-1} w)^T
        if (tid < NX) {
            const float un = W[tid*WST + 64] * rstd_s[tid];
            u_s[tid] = un;
            if (mainrow) g_u[r*NX + tid] = un;
        }
        __syncthreads();

        // pred' = P - off off^T = P - offT^T offT
        #pragma unroll
        for (int t = 0; t < 2; t++) {
            const int i = i0 + 16*t;
            float s = P_s[i*33 + j0];
            #pragma unroll
            for (int k = 0; k < NX; k++) s -= offT[k*33 + i] * offT[k*33 + j0];
            pred[i*33 + j0] = s;
        }
        __syncthreads();
    }
}

// ---------------------------------------------------------------------------
// Backward: chunked reverse scan with warm-up. Pure dense matmuls per step:
//   tmp = g - vw @ off ;  vw = tmp @ Linv   (Linv stored transposed)
// 16 KB/step register-prefetched (double-buffered through registers).
// ---------------------------------------------------------------------------
__global__ __launch_bounds__(NT) void bwd_kernel(
    const float* __restrict__ epsx, float* __restrict__ out)
{
    __shared__ float vw  [65*33];
    __shared__ float tmp [65*33];
    __shared__ float linvT[NX*33];
    __shared__ float offt [NX*33];
    __shared__ float ebuf [NM*NX];   // stride 32 (row-wise reads only)
    __shared__ float u_row[NX];

    const int tid = threadIdx.x;
    const int b   = blockIdx.x;
    const int rlow     = b*BW_S;
    const int rmainTop = rlow + BW_S - 1;
    int rtop = rmainTop + BW_W; if (rtop > RR-1) rtop = RR-1;  // clamp = exact init
    const int nsteps = rtop - rlow + 1;

    for (int idx = tid; idx < 65*33; idx += NT) vw[idx] = 0.f;

    float4 lo4, ev4; float uva = 0.f;
    {   // initial prefetch
        const size_t rb = (size_t)rtop * 1024;
        if (tid < 256) lo4 = reinterpret_cast<const float4*>(g_linvT + rb)[tid];
        else           lo4 = reinterpret_cast<const float4*>(g_offT  + rb)[tid - 256];
        ev4 = reinterpret_cast<const float4*>(epsx + (size_t)rtop*2048)[tid];
        if (tid < 32) uva = g_u[rtop*NX + tid];
    }
    __syncthreads();

    for (int step = 0; step < nsteps; step++) {
        const int r = rtop - step;

        // stage prefetched tiles into padded smem
        if (tid < 256) {
            const int idx = tid*4, i = idx >> 5, c = idx & 31;
            float* p = &linvT[i*33 + c];
            p[0]=lo4.x; p[1]=lo4.y; p[2]=lo4.z; p[3]=lo4.w;
        } else {
            const int idx = (tid-256)*4, i = idx >> 5, c = idx & 31;
            float* p = &offt[i*33 + c];
            p[0]=lo4.x; p[1]=lo4.y; p[2]=lo4.z; p[3]=lo4.w;
        }
        {
            float* p = &ebuf[tid*4];
            p[0]=ev4.x; p[1]=ev4.y; p[2]=ev4.z; p[3]=ev4.w;
        }
        if (tid < 32) u_row[tid] = uva;

        // prefetch next (latency hidden under the two matmul phases)
        if (step + 1 < nsteps) {
            const size_t rb = (size_t)(r-1) * 1024;
            if (tid < 256) lo4 = reinterpret_cast<const float4*>(g_linvT + rb)[tid];
            else           lo4 = reinterpret_cast<const float4*>(g_offT  + rb)[tid - 256];
            ev4 = reinterpret_cast<const float4*>(epsx + (size_t)(r-1)*2048)[tid];
            if (tid < 32) uva = g_u[(r-1)*NX + tid];
        }
        __syncthreads();

        // phase 1: tmp[m][j] = g[m][j] - sum_i vw[m][i] * off[i][j]
        for (int idx = tid; idx < 65*NX; idx += NT) {
            const int m = idx >> 5, j = idx & 31;
            float s = (m == 0) ? u_row[j] : ebuf[(m-1)*NX + j];
            #pragma unroll
            for (int i = 0; i < NX; i++) s -= vw[m*33 + i] * offt[j*33 + i];
            tmp[m*33 + j] = s;
        }
        __syncthreads();

        // phase 2: vw[m][i] = sum_j tmp[m][j] * Linv[j][i]  (= tmp @ Linv)
        for (int idx = tid; idx < 65*NX; idx += NT) {
            const int m = idx >> 5, i = idx & 31;
            float s = 0.f;
            #pragma unroll
            for (int j = 0; j < NX; j++) s += tmp[m*33 + j] * linvT[i*33 + j];
            vw[m*33 + i] = s;
        }
        __syncthreads();

        // output: out[r][m][i] = vs + ws = vw[0][i] + vw[m+1][i]
        if (r <= rmainTop) {
            float* orow = out + (size_t)r * (NM*NX);
            for (int idx = tid; idx < NM*NX; idx += NT) {
                const int m = idx >> 5, i = idx & 31;
                orow[idx] = vw[i] + vw[(m+1)*33 + i];
            }
        }
        __syncthreads();
    }
}

extern "C" void kernel_launch(void* const* d_in, const int* in_sizes, int n_in,
                              void* d_out, int out_size) {
    const float* hess  = (const float*)d_in[0];   // (8192,32,32)
    const float* grads = (const float*)d_in[1];   // (8192,1,32)
    const float* Amat  = (const float*)d_in[2];   // (32,32)
    const float* Ptp   = (const float*)d_in[3];   // (32,32)
    const float* Pinit = (const float*)d_in[4];   // (32,32)
    const float* epsx  = (const float*)d_in[5];   // (8192,64,32)
    float* out = (float*)d_out;                   // (8192,64,32)
    (void)in_sizes; (void)n_in; (void)out_size;

    fwd_kernel<<<FW_BLOCKS, NT>>>(hess, grads, Amat, Ptp, Pinit);
    bwd_kernel<<<BW_BLOCKS, NT>>>(epsx, out);
}

// round 4
// speedup vs baseline: 2.0220x; 2.0220x over previous
#include <cuda_runtime.h>
#include <cstdint>

#define RR 8192
#define NX 32
#define WST 104            // row stride of augmented W (8 mod 32 -> conflict-free 4x8 layout)
// augmented columns: [0,32) M | [32,64) -ap | 64 w | [65,97) I
#define FW_S 16
#define FW_W 64
#define FW_BLOCKS (RR/FW_S)   // 512
#define FNT 256
#define BW_S 64
#define BW_W 64
#define BW_BLOCKS (RR/BW_S)   // 128
#define BNT 512
#define PNT 256

// Forward products
__device__ float g_linvT[RR*NX*NX];   // [r][i][j] = Linv[j][i]
__device__ float g_offT [RR*NX*NX];   // [r][k][j] = off[j][k]
__device__ float g_u    [RR*NX];
// prep products
__device__ float g_ZT   [RR*NX*NX];   // [r][i][j] = Z[j][i],  Z = off @ Linv
__device__ float g_G    [RR*65*NX];   // [r][m][i] = (g @ Linv)[m][i]

// ---------------------------------------------------------------------------
// Forward: chunked scan (warm-up 64). Rank-2 blocked LDL^T elimination on the
// augmented matrix [M | -ap | w | I]: ONE barrier per pivot PAIR. Row k+1 is
// never written during its own round; its final values are reconstructed at
// extraction via stored p (multiplier) and d1 (pivot).
// ---------------------------------------------------------------------------
__global__ __launch_bounds__(FNT, 4) void fwd_kernel(
    const float* __restrict__ hess, const float* __restrict__ grads,
    const float* __restrict__ Amat, const float* __restrict__ Ptp,
    const float* __restrict__ Pinit)
{
    __shared__ float W[NX*WST];
    __shared__ float pred[NX*33];
    __shared__ float offT[NX*33];
    __shared__ float ap_s[NX*33];
    __shared__ float apat_s[NX*33];
    __shared__ float P_s[NX*33];
    __shared__ float A_s[NX*33];
    __shared__ float u_s[NX];
    __shared__ float pcof[16];
    __shared__ float dfin[16];

    const int tid = threadIdx.x;
    const int b   = blockIdx.x;
    int r0 = b*FW_S - FW_W; if (r0 < 0) r0 = 0;
    const int rend  = (b+1)*FW_S;
    const int rmain = b*FW_S;
    const int nsteps = rend - r0;
    const bool exact = (r0 == 0);

    for (int idx = tid; idx < NX*NX; idx += FNT) {
        int i = idx >> 5, j = idx & 31;
        A_s [i*33+j] = Amat[idx];
        P_s [i*33+j] = Ptp[idx];
        pred[i*33+j] = exact ? Pinit[idx] : Ptp[idx];
        offT[i*33+j] = 0.f;
    }
    if (tid < NX) u_s[tid] = 0.f;
    __syncthreads();
    for (int idx = tid; idx < NX*NX; idx += FNT) {   // ap = A @ Ptp
        int i = idx >> 5, j = idx & 31;
        float s = 0.f;
        #pragma unroll
        for (int k = 0; k < NX; k++) s += A_s[i*33+k]*P_s[k*33+j];
        ap_s[i*33+j] = s;
    }
    __syncthreads();
    for (int idx = tid; idx < NX*NX; idx += FNT) {   // apat = ap @ A^T
        int i = idx >> 5, j = idx & 31;
        float s = 0.f;
        #pragma unroll
        for (int k = 0; k < NX; k++) s += ap_s[i*33+k]*A_s[j*33+k];
        apat_s[i*33+j] = s;
    }
    __syncthreads();

    // register prefetch of first step's hess / grad
    float h0 = hess[(size_t)r0*1024 + tid];
    float h1 = hess[(size_t)r0*1024 + 256 + tid];
    float h2 = hess[(size_t)r0*1024 + 512 + tid];
    float h3 = hess[(size_t)r0*1024 + 768 + tid];
    float gpre = (tid < NX) ? grads[r0*NX + tid] : 0.f;

    const int rowoff = tid >> 3;   // 0..31
    const int lane8  = tid & 7;

    for (int step = 0; step < nsteps; step++) {
        const int r = r0 + step;
        const float mfac = (r == RR-1) ? 0.f : 1.f;

        // ---- build augmented W ----
        {
            float hv[4] = {h0, h1, h2, h3};
            #pragma unroll
            for (int t = 0; t < 4; t++) {
                const int idx = tid + FNT*t;
                const int i = idx >> 5, j = idx & 31;
                W[i*WST + j]      = pred[i*33+j] + hv[t] + mfac*apat_s[i*33+j];
                W[i*WST + 32 + j] = -ap_s[i*33+j];
                W[i*WST + 65 + j] = (i == j) ? 1.f : 0.f;
            }
        }
        if (tid < NX) {   // w = grad - u @ off^T  (previous step's off, u)
            float wv = gpre;
            #pragma unroll
            for (int k = 0; k < NX; k++) wv -= u_s[k]*offT[k*33 + tid];
            W[tid*WST + 64] = wv;
        }
        if (step + 1 < nsteps) {   // prefetch next step (hidden under elimination)
            h0 = hess[(size_t)(r+1)*1024 + tid];
            h1 = hess[(size_t)(r+1)*1024 + 256 + tid];
            h2 = hess[(size_t)(r+1)*1024 + 512 + tid];
            h3 = hess[(size_t)(r+1)*1024 + 768 + tid];
            if (tid < NX) gpre = grads[(r+1)*NX + tid];
        }
        __syncthreads();

        // ---- rank-2 blocked elimination: 16 rounds, 1 barrier each ----
        for (int rd = 0; rd < 16; rd++) {
            const int k = rd << 1;
            const float dk    = W[k*WST + k];
            const float invdk = __frcp_rn(dk);
            const float wkk1  = W[k*WST + k + 1];
            const float p     = W[(k+1)*WST + k] * invdk;
            const float d1    = W[(k+1)*WST + k + 1] - p*wkk1;
            const float invd1 = __frcp_rn(d1);
            if (tid == 0) { pcof[rd] = p; dfin[rd] = d1; }
            const int i = k + 2 + rowoff;
            if (i < NX) {
                const float a  = W[i*WST + k] * invdk;
                const float bb = (W[i*WST + k + 1] - a*wkk1) * invd1;
                const float c0 = a - bb*p;
                const float c1 = bb;
                const float* rk  = &W[k*WST];
                const float* rk1 = &W[(k+1)*WST];
                float* ri = &W[i*WST];
                const int cend = 67 + k;   // I-cols beyond 65+k+1 are still zero in pivot rows
                for (int c = k + 2 + lane8; c < cend; c += 8)
                    ri[c] -= c0*rk[c] + c1*rk1[c];
            }
            __syncthreads();
        }

        // ---- extraction (odd rows corrected by -p * even row) ----
        const bool mainrow = (r >= rmain);
        const size_t rbase = (size_t)r * (NX*NX);

        #pragma unroll
        for (int t = 0; t < 4; t++) {   // offT (+ gmem)
            const int idx = tid + FNT*t;
            const int kk = idx >> 5, i = idx & 31;
            float v = W[kk*WST + 32 + i];
            float dv;
            if (kk & 1) { v -= pcof[kk>>1]*W[(kk-1)*WST + 32 + i]; dv = dfin[kk>>1]; }
            else dv = W[kk*WST + kk];
            const float ov = v * __frsqrt_rn(dv);
            offT[kk*33 + i] = ov;
            if (mainrow) g_offT[rbase + kk*NX + i] = ov;
        }
        if (mainrow) {   // g_linvT[r][c][kk] = Linv[kk][c]
            #pragma unroll
            for (int t = 0; t < 4; t++) {
                const int idx = tid + FNT*t;
                const int c = idx >> 5, kk = idx & 31;
                float v = W[kk*WST + 65 + c];
                float dv;
                if (kk & 1) { v -= pcof[kk>>1]*W[(kk-1)*WST + 65 + c]; dv = dfin[kk>>1]; }
                else dv = W[kk*WST + kk];
                g_linvT[rbase + c*NX + kk] = v * __frsqrt_rn(dv);
            }
        }
        if (tid < NX) {   // u' = (L^{-1} w)^T
            const int kk = tid;
            float v = W[kk*WST + 64];
            float dv;
            if (kk & 1) { v -= pcof[kk>>1]*W[(kk-1)*WST + 64]; dv = dfin[kk>>1]; }
            else dv = W[kk*WST + kk];
            const float un = v * __frsqrt_rn(dv);
            u_s[kk] = un;
            if (mainrow) g_u[r*NX + kk] = un;
        }
        __syncthreads();

        // ---- pred' = P - offT^T offT  (2x2 register tiles) ----
        {
            const int ti = (tid >> 4) << 1;
            const int tj = (tid & 15) << 1;
            float a00 = P_s[ti*33+tj],     a01 = P_s[ti*33+tj+1];
            float a10 = P_s[(ti+1)*33+tj], a11 = P_s[(ti+1)*33+tj+1];
            #pragma unroll
            for (int k = 0; k < NX; k++) {
                const float x0 = offT[k*33+ti], x1 = offT[k*33+ti+1];
                const float y0 = offT[k*33+tj], y1 = offT[k*33+tj+1];
                a00 -= x0*y0; a01 -= x0*y1; a10 -= x1*y0; a11 -= x1*y1;
            }
            pred[ti*33+tj] = a00;     pred[ti*33+tj+1] = a01;
            pred[(ti+1)*33+tj] = a10; pred[(ti+1)*33+tj+1] = a11;
        }
        __syncthreads();
    }
}

// ---------------------------------------------------------------------------
// prep: embarrassingly parallel per-r transforms for the backward scan.
//   ZT[i][j] = (off @ Linv)[j][i],  G[m][i] = (g @ Linv)[m][i],
//   g = [u ; eps rows]. Warp-per-row with broadcast LDS.
// ---------------------------------------------------------------------------
__global__ __launch_bounds__(PNT) void prep_kernel(const float* __restrict__ epsx)
{
    __shared__ float linvT_s[NX*33];
    __shared__ float offT_s[NX*33];
    __shared__ float g_s[65*NX];

    const int tid = threadIdx.x;
    const int r = blockIdx.x;
    const size_t rb = (size_t)r * (NX*NX);

    {   // stage linvT, offT (padded) and g (u + eps, unpadded)
        float4 v = reinterpret_cast<const float4*>(g_linvT + rb)[tid];
        int fi = tid*4, i = fi >> 5, k = fi & 31;
        float* p = &linvT_s[i*33 + k];
        p[0]=v.x; p[1]=v.y; p[2]=v.z; p[3]=v.w;
        v = reinterpret_cast<const float4*>(g_offT + rb)[tid];
        p = &offT_s[i*33 + k];
        p[0]=v.x; p[1]=v.y; p[2]=v.z; p[3]=v.w;
    }
    if (tid < NX) g_s[tid] = g_u[r*NX + tid];
    {
        const float4* esrc = reinterpret_cast<const float4*>(epsx + (size_t)r*2048);
        float4* edst = reinterpret_cast<float4*>(&g_s[NX]);
        edst[tid]       = esrc[tid];
        edst[tid + PNT] = esrc[tid + PNT];
    }
    __syncthreads();

    const int lane = tid & 31, w = tid >> 5;   // 8 warps
    for (int m = w; m < 65; m += 8) {          // G rows
        const float* grow = &g_s[m*NX];
        float a0 = 0.f, a1 = 0.f;
        #pragma unroll
        for (int k = 0; k < NX; k += 2) {
            a0 += grow[k]   * linvT_s[lane*33 + k];
            a1 += grow[k+1] * linvT_s[lane*33 + k + 1];
        }
        g_G[(size_t)r*2080 + m*NX + lane] = a0 + a1;
    }
    for (int i = w; i < NX; i += 8) {          // ZT rows
        float a0 = 0.f, a1 = 0.f;
        #pragma unroll
        for (int k = 0; k < NX; k += 2) {
            a0 += offT_s[k*33 + lane]     * linvT_s[i*33 + k];
            a1 += offT_s[(k+1)*33 + lane] * linvT_s[i*33 + k + 1];
        }
        g_ZT[rb + i*NX + lane] = a0 + a1;
    }
}

// ---------------------------------------------------------------------------
// Backward: chunked reverse scan (warm-up 64). ONE fused matmul per step:
//   vw' = G' - vw @ Z   (Z row cached in registers, vw via broadcast LDS)
// ---------------------------------------------------------------------------
__device__ __forceinline__ float4 ldtile(int r, int idx) {
    if (idx < 256) return reinterpret_cast<const float4*>(g_ZT + (size_t)r*1024)[idx];
    return reinterpret_cast<const float4*>(g_G + (size_t)r*2080)[idx - 256];
}

__global__ __launch_bounds__(BNT) void bwd_kernel(float* __restrict__ out)
{
    __shared__ float vw[65*33];
    __shared__ float zt_s[NX*33];
    __shared__ __align__(16) float gbuf[65*NX];

    const int tid = threadIdx.x;
    const int b   = blockIdx.x;
    const int rlow     = b*BW_S;
    const int rmainTop = rlow + BW_S - 1;
    int rtop = rmainTop + BW_W; if (rtop > RR-1) rtop = RR-1;
    const int nsteps = rtop - rlow + 1;

    for (int idx = tid; idx < 65*33; idx += BNT) vw[idx] = 0.f;

    // 776 float4 tiles per step: 256 (ZT) + 520 (G)
    float4 f0 = ldtile(rtop, tid);
    float4 f1 = (tid < 264) ? ldtile(rtop, tid + BNT) : make_float4(0,0,0,0);

    const int lane = tid & 31, w = tid >> 5;   // 16 warps

    for (int step = 0; step < nsteps; step++) {
        const int r = rtop - step;

        // stage prefetched tiles
        {
            if (tid < 256) {
                int fi = tid*4, i = fi >> 5, j = fi & 31;
                float* p = &zt_s[i*33 + j];
                p[0]=f0.x; p[1]=f0.y; p[2]=f0.z; p[3]=f0.w;
            } else {
                reinterpret_cast<float4*>(gbuf)[tid - 256] = f0;
            }
            if (tid < 264) reinterpret_cast<float4*>(gbuf)[tid + BNT - 256] = f1;
        }
        if (step + 1 < nsteps) {
            f0 = ldtile(r-1, tid);
            if (tid < 264) f1 = ldtile(r-1, tid + BNT);
        }
        __syncthreads();

        float ztr[NX];
        #pragma unroll
        for (int j = 0; j < NX; j++) ztr[j] = zt_s[lane*33 + j];

        for (int m = w; m < 65; m += 16) {
            float a0 = gbuf[m*NX + lane], a1 = 0.f;
            #pragma unroll
            for (int j = 0; j < NX; j += 2) {
                a0 -= vw[m*33 + j]     * ztr[j];
                a1 += vw[m*33 + j + 1] * ztr[j+1];
            }
            vw[m*33 + lane] = a0 - a1;
        }
        __syncthreads();

        if (r <= rmainTop) {
            float* orow = out + (size_t)r * 2048;
            #pragma unroll
            for (int t = 0; t < 4; t++) {
                const int idx = tid + BNT*t;
                const int m = idx >> 5, i = idx & 31;
                orow[idx] = vw[i] + vw[(m+1)*33 + i];
            }
        }
    }
}

extern "C" void kernel_launch(void* const* d_in, const int* in_sizes, int n_in,
                              void* d_out, int out_size) {
    const float* hess  = (const float*)d_in[0];   // (8192,32,32)
    const float* grads = (const float*)d_in[1];   // (8192,1,32)
    const float* Amat  = (const float*)d_in[2];   // (32,32)
    const float* Ptp   = (const float*)d_in[3];   // (32,32)
    const float* Pinit = (const float*)d_in[4];   // (32,32)
    const float* epsx  = (const float*)d_in[5];   // (8192,64,32)
    float* out = (float*)d_out;                   // (8192,64,32)
    (void)in_sizes; (void)n_in; (void)out_size;

    fwd_kernel<<<FW_BLOCKS, FNT>>>(hess, grads, Amat, Ptp, Pinit);
    prep_kernel<<<RR, PNT>>>(epsx);
    bwd_kernel<<<BW_BLOCKS, BNT>>>(out);
}

// round 6
// speedup vs baseline: 2.4097x; 1.1917x over previous
#include <cuda_runtime.h>
#include <cstdint>

#define RR 8192
#define NX 32
#define WST 72             // row stride (8 mod 32 -> conflict-free 4x8 access)
// augmented columns: [0,32) M | [32,64) -ap | 64 w
#define FW_S 16
#define FW_W 40
#define FW_BLOCKS (RR/FW_S)   // 512
#define FNT 256
#define BW_S 64
#define BW_W 40
#define BW_BLOCKS (RR/BW_S)   // 128
#define BNT 1024
#define PNT 256

// Forward products
__device__ float g_Lhat[RR*NX*NX];   // [r][k][i]: i>k: L[i][k]; i==k: rstd_k; i<k: 0
__device__ float g_offT[RR*NX*NX];   // [r][k][j] = off[j][k]
__device__ float g_u   [RR*NX];
// prep products
__device__ float g_ZT  [RR*NX*NX];   // [r][i][j] = Z[j][i],  Z = off @ Linv
__device__ float g_G   [RR*65*NX];   // [r][m][i] = (g @ Linv)[m][i]

// ---------------------------------------------------------------------------
// Forward: chunked scan (warm-up 40). Rank-2 blocked LDL^T elimination on the
// augmented matrix [M | -ap | w]: ONE barrier per pivot PAIR. The identity /
// L-inverse block is NOT carried — L is recovered from the eliminated upper
// rows of the M block at extraction (Uhat[k][i] = d_k * Ltilde[i][k]).
// ---------------------------------------------------------------------------
__global__ __launch_bounds__(FNT, 4) void fwd_kernel(
    const float* __restrict__ hess, const float* __restrict__ grads,
    const float* __restrict__ Amat, const float* __restrict__ Ptp,
    const float* __restrict__ Pinit)
{
    __shared__ float W[NX*WST];
    __shared__ float pred[NX*33];
    __shared__ float offT[NX*33];
    __shared__ float ap_s[NX*33];
    __shared__ float apat_s[NX*33];
    __shared__ float P_s[NX*33];
    __shared__ float A_s[NX*33];
    __shared__ float u_s[NX];
    __shared__ float pcof[16];
    __shared__ float dfin[16];

    const int tid = threadIdx.x;
    const int b   = blockIdx.x;
    int r0 = b*FW_S - FW_W; if (r0 < 0) r0 = 0;
    const int rend  = (b+1)*FW_S;
    const int rmain = b*FW_S;
    const int nsteps = rend - r0;
    const bool exact = (r0 == 0);

    for (int idx = tid; idx < NX*NX; idx += FNT) {
        int i = idx >> 5, j = idx & 31;
        A_s [i*33+j] = Amat[idx];
        P_s [i*33+j] = Ptp[idx];
        pred[i*33+j] = exact ? Pinit[idx] : Ptp[idx];
        offT[i*33+j] = 0.f;
    }
    if (tid < NX) u_s[tid] = 0.f;
    __syncthreads();
    for (int idx = tid; idx < NX*NX; idx += FNT) {   // ap = A @ Ptp
        int i = idx >> 5, j = idx & 31;
        float s = 0.f;
        #pragma unroll
        for (int k = 0; k < NX; k++) s += A_s[i*33+k]*P_s[k*33+j];
        ap_s[i*33+j] = s;
    }
    __syncthreads();
    for (int idx = tid; idx < NX*NX; idx += FNT) {   // apat = ap @ A^T
        int i = idx >> 5, j = idx & 31;
        float s = 0.f;
        #pragma unroll
        for (int k = 0; k < NX; k++) s += ap_s[i*33+k]*A_s[j*33+k];
        apat_s[i*33+j] = s;
    }
    __syncthreads();

    // register prefetch of first step's hess / grad
    float h0 = hess[(size_t)r0*1024 + tid];
    float h1 = hess[(size_t)r0*1024 + 256 + tid];
    float h2 = hess[(size_t)r0*1024 + 512 + tid];
    float h3 = hess[(size_t)r0*1024 + 768 + tid];
    float gpre = (tid < NX) ? grads[r0*NX + tid] : 0.f;

    const int rowoff = tid >> 3;   // 0..31
    const int lane8  = tid & 7;

    for (int step = 0; step < nsteps; step++) {
        const int r = r0 + step;
        const float mfac = (r == RR-1) ? 0.f : 1.f;

        // ---- build augmented W = [pred+hess+m*apat | -ap | w] ----
        {
            float hv[4] = {h0, h1, h2, h3};
            #pragma unroll
            for (int t = 0; t < 4; t++) {
                const int idx = tid + FNT*t;
                const int i = idx >> 5, j = idx & 31;
                W[i*WST + j]      = pred[i*33+j] + hv[t] + mfac*apat_s[i*33+j];
                W[i*WST + 32 + j] = -ap_s[i*33+j];
            }
        }
        if (tid < NX) {   // w = grad - u @ off^T  (previous step's off, u)
            float wv = gpre;
            #pragma unroll
            for (int k = 0; k < NX; k++) wv -= u_s[k]*offT[k*33 + tid];
            W[tid*WST + 64] = wv;
        }
        if (step + 1 < nsteps) {   // prefetch next step (hidden under elimination)
            h0 = hess[(size_t)(r+1)*1024 + tid];
            h1 = hess[(size_t)(r+1)*1024 + 256 + tid];
            h2 = hess[(size_t)(r+1)*1024 + 512 + tid];
            h3 = hess[(size_t)(r+1)*1024 + 768 + tid];
            if (tid < NX) gpre = grads[(r+1)*NX + tid];
        }
        __syncthreads();

        // ---- rank-2 blocked elimination: 16 rounds, 1 barrier each ----
        for (int rd = 0; rd < 16; rd++) {
            const int k = rd << 1;
            const float dk    = W[k*WST + k];
            const float invdk = __frcp_rn(dk);
            const float wkk1  = W[k*WST + k + 1];
            const float p     = W[(k+1)*WST + k] * invdk;
            const float d1    = W[(k+1)*WST + k + 1] - p*wkk1;
            const float invd1 = __frcp_rn(d1);
            if (tid == 0) { pcof[rd] = p; dfin[rd] = d1; }
            const int i = k + 2 + rowoff;
            if (i < NX) {
                const float a  = W[i*WST + k] * invdk;
                const float bb = (W[i*WST + k + 1] - a*wkk1) * invd1;
                const float c0 = a - bb*p;
                const float c1 = bb;
                const float* rk  = &W[k*WST];
                const float* rk1 = &W[(k+1)*WST];
                float* ri = &W[i*WST];
                for (int c = k + 2 + lane8; c < 65; c += 8)
                    ri[c] -= c0*rk[c] + c1*rk1[c];
            }
            __syncthreads();
        }

        // ---- extraction (odd rows corrected by -p * even row) ----
        const bool mainrow = (r >= rmain);
        const size_t rbase = (size_t)r * (NX*NX);

        #pragma unroll
        for (int t = 0; t < 4; t++) {   // offT (+ gmem)
            const int idx = tid + FNT*t;
            const int kk = idx >> 5, i = idx & 31;
            float v = W[kk*WST + 32 + i];
            float dv;
            if (kk & 1) { v -= pcof[kk>>1]*W[(kk-1)*WST + 32 + i]; dv = dfin[kk>>1]; }
            else dv = W[kk*WST + kk];
            const float ov = v * __frsqrt_rn(dv);
            offT[kk*33 + i] = ov;
            if (mainrow) g_offT[rbase + kk*NX + i] = ov;
        }
        if (mainrow) {   // scaled-L^T: g_Lhat[r][kk][c] = Uhat[kk][c]*rstd_kk = L[c][kk]
            #pragma unroll
            for (int t = 0; t < 4; t++) {
                const int idx = tid + FNT*t;
                const int kk = idx >> 5, c = idx & 31;
                float v = W[kk*WST + c];
                float dv;
                if (kk & 1) { v -= pcof[kk>>1]*W[(kk-1)*WST + c]; dv = dfin[kk>>1]; }
                else dv = W[kk*WST + kk];
                const float rs = __frsqrt_rn(dv);
                const float outv = (c > kk) ? v*rs : ((c == kk) ? rs : 0.f);
                g_Lhat[rbase + kk*NX + c] = outv;
            }
        }
        if (tid < NX) {   // u' = (L^{-1} w)^T
            const int kk = tid;
            float v = W[kk*WST + 64];
            float dv;
            if (kk & 1) { v -= pcof[kk>>1]*W[(kk-1)*WST + 64]; dv = dfin[kk>>1]; }
            else dv = W[kk*WST + kk];
            const float un = v * __frsqrt_rn(dv);
            u_s[kk] = un;
            if (mainrow) g_u[r*NX + kk] = un;
        }
        __syncthreads();

        // ---- pred' = P - offT^T offT  (2x2 register tiles) ----
        {
            const int ti = (tid >> 4) << 1;
            const int tj = (tid & 15) << 1;
            float a00 = P_s[ti*33+tj],     a01 = P_s[ti*33+tj+1];
            float a10 = P_s[(ti+1)*33+tj], a11 = P_s[(ti+1)*33+tj+1];
            #pragma unroll
            for (int k = 0; k < NX; k++) {
                const float x0 = offT[k*33+ti], x1 = offT[k*33+ti+1];
                const float y0 = offT[k*33+tj], y1 = offT[k*33+tj+1];
                a00 -= x0*y0; a01 -= x0*y1; a10 -= x1*y0; a11 -= x1*y1;
            }
            pred[ti*33+tj] = a00;     pred[ti*33+tj+1] = a01;
            pred[(ti+1)*33+tj] = a10; pred[(ti+1)*33+tj+1] = a11;
        }
        __syncthreads();
    }
}

// ---------------------------------------------------------------------------
// prep: per-r (parallel) — invert L by 32 independent column substitutions,
// then ZT[i][j] = (off @ Linv)[j][i] and G[m][i] = (g @ Linv)[m][i],
// g = [u ; eps rows].
// ---------------------------------------------------------------------------
__global__ __launch_bounds__(PNT) void prep_kernel(const float* __restrict__ epsx)
{
    __shared__ float Lh_s[NX*33];     // Lh_s[k*33+i] = L[i][k] (i>k), diag = rstd_k
    __shared__ float linvT_s[NX*33];  // linvT_s[j*33+i] = Linv[i][j]
    __shared__ float offT_s[NX*33];
    __shared__ float g_s[65*NX];

    const int tid = threadIdx.x;
    const int r = blockIdx.x;
    const size_t rb = (size_t)r * (NX*NX);

    {   // stage Lhat, offT (padded) and g (u + eps, unpadded)
        float4 v = reinterpret_cast<const float4*>(g_Lhat + rb)[tid];
        int fi = tid*4, i = fi >> 5, k = fi & 31;
        float* p = &Lh_s[i*33 + k];
        p[0]=v.x; p[1]=v.y; p[2]=v.z; p[3]=v.w;
        v = reinterpret_cast<const float4*>(g_offT + rb)[tid];
        p = &offT_s[i*33 + k];
        p[0]=v.x; p[1]=v.y; p[2]=v.z; p[3]=v.w;
    }
    for (int idx = tid; idx < NX*33; idx += PNT) linvT_s[idx] = 0.f;
    if (tid < NX) g_s[tid] = g_u[r*NX + tid];
    {
        const float4* esrc = reinterpret_cast<const float4*>(epsx + (size_t)r*2048);
        float4* edst = reinterpret_cast<float4*>(&g_s[NX]);
        edst[tid]       = esrc[tid];
        edst[tid + PNT] = esrc[tid + PNT];
    }
    __syncthreads();

    // ---- invert L: lane j computes Linv column j (warp 0) ----
    if (tid < NX) {
        const int j = tid;
        linvT_s[j*33 + j] = Lh_s[j*33 + j];   // X[j][j] = rstd_j
        for (int i = 1; i < NX; i++) {
            if (j < i) {
                float s0 = 0.f, s1 = 0.f;
                int k = j;
                for (; k + 1 < i; k += 2) {
                    s0 += Lh_s[k*33 + i]     * linvT_s[j*33 + k];
                    s1 += Lh_s[(k+1)*33 + i] * linvT_s[j*33 + k + 1];
                }
                if (k < i) s0 += Lh_s[k*33 + i] * linvT_s[j*33 + k];
                linvT_s[j*33 + i] = -Lh_s[i*33 + i] * (s0 + s1);
            }
        }
    }
    __syncthreads();

    const int lane = tid & 31, w = tid >> 5;   // 8 warps
    for (int m = w; m < 65; m += 8) {          // G rows
        const float* grow = &g_s[m*NX];
        float a0 = 0.f, a1 = 0.f;
        #pragma unroll
        for (int k = 0; k < NX; k += 2) {
            a0 += grow[k]   * linvT_s[lane*33 + k];
            a1 += grow[k+1] * linvT_s[lane*33 + k + 1];
        }
        g_G[(size_t)r*2080 + m*NX + lane] = a0 + a1;
    }
    for (int i = w; i < NX; i += 8) {          // ZT rows
        float a0 = 0.f, a1 = 0.f;
        #pragma unroll
        for (int k = 0; k < NX; k += 2) {
            a0 += offT_s[k*33 + lane]     * linvT_s[i*33 + k];
            a1 += offT_s[(k+1)*33 + lane] * linvT_s[i*33 + k + 1];
        }
        g_ZT[rb + i*NX + lane] = a0 + a1;
    }
}

// ---------------------------------------------------------------------------
// Backward: chunked reverse scan (warm-up 40). ONE fused matmul per step:
//   vw' = G' - vw @ Z   (Z row cached in registers, vw via broadcast LDS)
// ---------------------------------------------------------------------------
__device__ __forceinline__ float4 ldtile(int r, int idx) {
    if (idx < 256) return reinterpret_cast<const float4*>(g_ZT + (size_t)r*1024)[idx];
    return reinterpret_cast<const float4*>(g_G + (size_t)r*2080)[idx - 256];
}

__global__ __launch_bounds__(BNT) void bwd_kernel(float* __restrict__ out)
{
    __shared__ float vw[65*33];
    __shared__ float zt_s[NX*33];
    __shared__ __align__(16) float gbuf[65*NX];

    const int tid = threadIdx.x;
    const int b   = blockIdx.x;
    const int rlow     = b*BW_S;
    const int rmainTop = rlow + BW_S - 1;
    int rtop = rmainTop + BW_W; if (rtop > RR-1) rtop = RR-1;
    const int nsteps = rtop - rlow + 1;

    for (int idx = tid; idx < 65*33; idx += BNT) vw[idx] = 0.f;

    // 776 float4 tiles per step: 256 (ZT) + 520 (G)
    float4 f0 = (tid < 776) ? ldtile(rtop, tid) : make_float4(0,0,0,0);

    const int lane = tid & 31, w = tid >> 5;   // 32 warps

    for (int step = 0; step < nsteps; step++) {
        const int r = rtop - step;

        // stage prefetched tiles
        if (tid < 256) {
            int fi = tid*4, i = fi >> 5, j = fi & 31;
            float* p = &zt_s[i*33 + j];
            p[0]=f0.x; p[1]=f0.y; p[2]=f0.z; p[3]=f0.w;
        } else if (tid < 776) {
            reinterpret_cast<float4*>(gbuf)[tid - 256] = f0;
        }
        if (step + 1 < nsteps && tid < 776) f0 = ldtile(r-1, tid);
        __syncthreads();

        float ztr[NX];
        #pragma unroll
        for (int j = 0; j < NX; j++) ztr[j] = zt_s[lane*33 + j];

        for (int m = w; m < 65; m += 32) {
            float a0 = gbuf[m*NX + lane], a1 = 0.f;
            #pragma unroll
            for (int j = 0; j < NX; j += 2) {
                a0 -= vw[m*33 + j]     * ztr[j];
                a1 += vw[m*33 + j + 1] * ztr[j+1];
            }
            vw[m*33 + lane] = a0 - a1;
        }
        __syncthreads();

        if (r <= rmainTop) {
            float* orow = out + (size_t)r * 2048;
            #pragma unroll
            for (int t = 0; t < 2; t++) {
                const int idx = tid + BNT*t;
                const int m = idx >> 5, i = idx & 31;
                orow[idx] = vw[i] + vw[(m+1)*33 + i];
            }
        }
    }
}

extern "C" void kernel_launch(void* const* d_in, const int* in_sizes, int n_in,
                              void* d_out, int out_size) {
    const float* hess  = (const float*)d_in[0];   // (8192,32,32)
    const float* grads = (const float*)d_in[1];   // (8192,1,32)
    const float* Amat  = (const float*)d_in[2];   // (32,32)
    const float* Ptp   = (const float*)d_in[3];   // (32,32)
    const float* Pinit = (const float*)d_in[4];   // (32,32)
    const float* epsx  = (const float*)d_in[5];   // (8192,64,32)
    float* out = (float*)d_out;                   // (8192,64,32)
    (void)in_sizes; (void)n_in; (void)out_size;

    fwd_kernel<<<FW_BLOCKS, FNT>>>(hess, grads, Amat, Ptp, Pinit);
    prep_kernel<<<RR, PNT>>>(epsx);
    bwd_kernel<<<BW_BLOCKS, BNT>>>(out);
}

// round 8
// speedup vs baseline: 3.5577x; 1.4764x over previous
#include <cuda_runtime.h>
#include <cstdint>

#define RR 8192
#define NX 32
#define FW_S 8
#define FW_W 24
#define NCHAIN (RR/FW_S)         // 1024 chains, one warp each
#define FWPB 4                   // warps per block
#define FW_BLOCKS (NCHAIN/FWPB)  // 256
#define BW_S 64
#define BW_W 24
#define BW_BLOCKS (RR/BW_S)      // 128
#define BNT 1024
#define PNT 256
#define FULLM 0xffffffffu

// forward products
__device__ float g_Uh [RR*NX*NX];  // [r][j][k] = Uhat[k][j] (valid k<=j; junk below)
__device__ float g_off[RR*NX*NX];  // [r][j][k] = off[j][k]  (row-major off)
__device__ float g_rs [RR*NX];     // rstd diag
__device__ float g_u  [RR*NX];
// prep products
__device__ float g_ZT [RR*NX*NX];  // [r][i][j] = Z[j][i], Z = off @ Linv
__device__ float g_G  [RR*65*NX];  // [r][m][i] = (g @ Linv)[m][i]

// ---------------------------------------------------------------------------
// Forward: one WARP per chain (warm-up 24). The 32x65 augmented system
// [M | -ap | w] lives column-per-lane in registers; Gaussian elimination via
// warp shuffles — zero block barriers. w eliminated in a post-pass using
// t_ik = Uhat[k][i]/d_k (already local to lane i). pred-downdate is fused
// into the next step's build via a per-warp smem copy of off.
// ---------------------------------------------------------------------------
__global__ __launch_bounds__(128) void fwd_kernel(
    const float* __restrict__ hess, const float* __restrict__ grads,
    const float* __restrict__ Amat, const float* __restrict__ Ptp,
    const float* __restrict__ Pinit)
{
    __shared__ __align__(16) float C1[NX*33];     // Ptp + apat   (columns: [i*33+j])
    __shared__ __align__(16) float C0[NX*33];     // Ptp          (last step, mfac=0)
    __shared__ __align__(16) float Ci[NX*33];     // Pinit + apat (r==0)
    __shared__ __align__(16) float nap[NX*33];    // -ap
    __shared__ __align__(16) float offp[FWPB][NX*36+4];  // per-warp offT, stride 36

    const int tid = threadIdx.x, lane = tid & 31, w = tid >> 5;

    // ---- block init: ap = A@Ptp, apat = ap@A^T, build C0/C1/Ci/nap ----
    {
        float* A_s = offp[0];          // temp (stride 33)
        float* P_s = offp[2];          // temp
        for (int idx = tid; idx < NX*NX; idx += 128) {
            int i = idx >> 5, j = idx & 31;
            A_s[i*33+j] = Amat[idx];
            P_s[i*33+j] = Ptp[idx];
        }
        __syncthreads();
        for (int idx = tid; idx < NX*NX; idx += 128) {  // nap = -(A@P)
            int i = idx >> 5, j = idx & 31;
            float s = 0.f;
            #pragma unroll
            for (int k = 0; k < NX; k++) s += A_s[i*33+k]*P_s[k*33+j];
            nap[i*33+j] = -s;
        }
        __syncthreads();
        for (int idx = tid; idx < NX*NX; idx += 128) {  // apat = ap@A^T; C's
            int i = idx >> 5, j = idx & 31;
            float s = 0.f;
            #pragma unroll
            for (int k = 0; k < NX; k++) s -= nap[i*33+k]*A_s[j*33+k];
            const float P = P_s[i*33+j];
            C1[i*33+j] = P + s;
            C0[i*33+j] = P;
            Ci[i*33+j] = Pinit[idx] + s;
        }
        __syncthreads();
    }

    const int chain = blockIdx.x*FWPB + w;
    const int rmain = chain*FW_S;
    int r0 = rmain - FW_W; if (r0 < 0) r0 = 0;
    const int nsteps = rmain + FW_S - r0;
    float* op = offp[w];

    float a[NX], b[NX], rsd[NX], offr[NX], hp[NX];
    float gv, wv, uacc = 0.f;

    #pragma unroll
    for (int k = 0; k < NX; k++) { offr[k] = 0.f; op[k*36+lane] = 0.f; }
    __syncwarp();

    #pragma unroll
    for (int i = 0; i < NX; i++) hp[i] = hess[(size_t)r0*1024 + i*32 + lane];
    gv = grads[r0*NX + lane];

    for (int step = 0; step < nsteps; step++) {
        const int r = r0 + step;
        const float* Cp = (r == 0) ? Ci : ((r == RR-1) ? C0 : C1);

        // ---- build: a = C + hess - off^T off   (col of M), b = -ap col ----
        #pragma unroll
        for (int i = 0; i < NX; i++) a[i] = Cp[i*33+lane] + hp[i];
        #pragma unroll
        for (int k = 0; k < NX; k++) {
            const float ok = offr[k];
            #pragma unroll
            for (int i4 = 0; i4 < NX; i4 += 4) {
                const float4 v = *(const float4*)&op[k*36 + i4];
                a[i4]   -= v.x*ok; a[i4+1] -= v.y*ok;
                a[i4+2] -= v.z*ok; a[i4+3] -= v.w*ok;
            }
        }
        #pragma unroll
        for (int i = 0; i < NX; i++) b[i] = nap[i*33+lane];
        wv = gv - uacc;   // w[lane] = grad[lane] - u . off[lane][:]

        if (step + 1 < nsteps) {   // prefetch next hess/grad under elimination
            #pragma unroll
            for (int i = 0; i < NX; i++) hp[i] = hess[(size_t)(r+1)*1024 + i*32 + lane];
            gv = grads[(r+1)*NX + lane];
        }

        // ---- shuffle elimination (no barriers) ----
        float dmine = 1.f;
        #pragma unroll
        for (int k = 0; k < NX; k++) {
            const float dk = __shfl_sync(FULLM, a[k], k);
            rsd[k] = dk;
            dmine = (lane == k) ? dk : dmine;
            const float invd = __frcp_rn(dk);
            #pragma unroll
            for (int i = k+1; i < NX; i++) {
                const float t = __shfl_sync(FULLM, a[i], k) * invd;
                a[i] -= t*a[k];
                b[i] -= t*b[k];
            }
        }
        #pragma unroll
        for (int k = 0; k < NX; k++) rsd[k] = __frsqrt_rn(rsd[k]);
        const float rsmine = __frsqrt_rn(dmine);

        // ---- eliminate w: t_ik = Uhat[k][i]*invd_k = a[k]*rs_k^2 (local) ----
        #pragma unroll
        for (int k = 0; k < NX; k++) {
            const float wk = __shfl_sync(FULLM, wv, k);
            const float t = (lane > k) ? a[k]*rsd[k]*rsd[k] : 0.f;
            wv -= t*wk;
        }

        // ---- extraction: off row, u-dot for next w, smem offT ----
        uacc = 0.f;
        #pragma unroll
        for (int k = 0; k < NX; k++) {
            offr[k] = b[k]*rsd[k];
            const float uk = __shfl_sync(FULLM, wv, k) * rsd[k];
            uacc += uk*offr[k];
            op[k*36+lane] = offr[k];
        }
        __syncwarp();

        if (r >= rmain) {
            const size_t rb = (size_t)r*(NX*NX) + lane*NX;
            #pragma unroll
            for (int k4 = 0; k4 < NX; k4 += 4) {
                *(float4*)&g_off[rb+k4] = make_float4(offr[k4],offr[k4+1],offr[k4+2],offr[k4+3]);
                *(float4*)&g_Uh [rb+k4] = make_float4(a[k4],a[k4+1],a[k4+2],a[k4+3]);
            }
            g_rs[r*NX+lane] = rsmine;
            g_u [r*NX+lane] = wv * rsmine;
        }
    }
}

// ---------------------------------------------------------------------------
// prep: per-r parallel — rebuild L from raw Uhat + rs, invert it (32
// independent column substitutions), then ZT = (off@Linv)^T and G = g@Linv.
// FIX (R8): L[i][k] = Uhat[k][i] * rs_k   (single rs — true Cholesky factor),
// not Uhat[k][i]*rs_k^2 (which is the unit-diagonal Ltilde and broke Linv).
// ---------------------------------------------------------------------------
__global__ __launch_bounds__(PNT) void prep_kernel(const float* __restrict__ epsx)
{
    __shared__ float Lh_s[NX*33];     // Lh_s[k*33+i] = L[i][k] (i>k), diag rs_k
    __shared__ float linvT_s[NX*33];  // [j*33+i] = Linv[i][j]
    __shared__ float off_s[NX*33];    // [j*33+k] = off[j][k]
    __shared__ float g_sm[65*NX];
    __shared__ float rs_s[NX];

    const int tid = threadIdx.x;
    const int r = blockIdx.x;
    const size_t rb = (size_t)r * (NX*NX);

    if (tid < NX) rs_s[tid] = g_rs[r*NX + tid];
    {   // off rows
        float4 v = ((const float4*)(g_off + rb))[tid];
        int fi = tid*4, j = fi >> 5, k = fi & 31;
        float* p = &off_s[j*33 + k];
        p[0]=v.x; p[1]=v.y; p[2]=v.z; p[3]=v.w;
    }
    if (tid < NX) g_sm[tid] = g_u[r*NX + tid];
    {
        const float4* es = (const float4*)(epsx + (size_t)r*2048);
        float4* ed = (float4*)&g_sm[NX];
        ed[tid] = es[tid]; ed[tid+PNT] = es[tid+PNT];
    }
    for (int idx = tid; idx < NX*33; idx += PNT) linvT_s[idx] = 0.f;
    __syncthreads();   // rs_s ready

    {   // L[i][k] = Uh[i][k]*rs_k (k<i), rs_k (k==i), 0 else
        float4 v = ((const float4*)(g_Uh + rb))[tid];
        int fi = tid*4, i = fi >> 5, k = fi & 31;
        float vv[4] = {v.x, v.y, v.z, v.w};
        #pragma unroll
        for (int c = 0; c < 4; c++) {
            const int kk = k + c;
            const float rs = rs_s[kk];
            const float val = (kk < i) ? vv[c]*rs : ((kk == i) ? rs : 0.f);
            Lh_s[kk*33 + i] = val;
        }
    }
    __syncthreads();

    // invert L: lane j computes Linv column j (warp 0)
    if (tid < NX) {
        const int j = tid;
        linvT_s[j*33 + j] = Lh_s[j*33 + j];   // 1/L[j][j] = rs_j
        for (int i = 1; i < NX; i++) {
            if (j < i) {
                float s0 = 0.f, s1 = 0.f;
                int k = j;
                for (; k + 1 < i; k += 2) {
                    s0 += Lh_s[k*33 + i]     * linvT_s[j*33 + k];
                    s1 += Lh_s[(k+1)*33 + i] * linvT_s[j*33 + k + 1];
                }
                if (k < i) s0 += Lh_s[k*33 + i] * linvT_s[j*33 + k];
                linvT_s[j*33 + i] = -Lh_s[i*33 + i] * (s0 + s1);
            }
        }
    }
    __syncthreads();

    const int lane = tid & 31, w = tid >> 5;   // 8 warps
    for (int m = w; m < 65; m += 8) {          // G rows
        const float* grow = &g_sm[m*NX];
        float a0 = 0.f, a1 = 0.f;
        #pragma unroll
        for (int k = 0; k < NX; k += 2) {
            a0 += grow[k]   * linvT_s[lane*33 + k];
            a1 += grow[k+1] * linvT_s[lane*33 + k + 1];
        }
        g_G[(size_t)r*2080 + m*NX + lane] = a0 + a1;
    }
    for (int i = w; i < NX; i += 8) {          // ZT rows
        float a0 = 0.f, a1 = 0.f;
        #pragma unroll
        for (int k = 0; k < NX; k += 2) {
            a0 += off_s[lane*33 + k]     * linvT_s[i*33 + k];
            a1 += off_s[lane*33 + k + 1] * linvT_s[i*33 + k + 1];
        }
        g_ZT[rb + i*NX + lane] = a0 + a1;
    }
}

// ---------------------------------------------------------------------------
// Backward: chunked reverse scan (warm-up 24). ONE fused matmul per step:
//   vw' = G' - vw @ Z
// ---------------------------------------------------------------------------
__device__ __forceinline__ float4 ldtile(int r, int idx) {
    if (idx < 256) return reinterpret_cast<const float4*>(g_ZT + (size_t)r*1024)[idx];
    return reinterpret_cast<const float4*>(g_G + (size_t)r*2080)[idx - 256];
}

__global__ __launch_bounds__(BNT) void bwd_kernel(float* __restrict__ out)
{
    __shared__ float vw[65*33];
    __shared__ float zt_s[NX*33];
    __shared__ __align__(16) float gbuf[65*NX];

    const int tid = threadIdx.x;
    const int b   = blockIdx.x;
    const int rlow     = b*BW_S;
    const int rmainTop = rlow + BW_S - 1;
    int rtop = rmainTop + BW_W; if (rtop > RR-1) rtop = RR-1;
    const int nsteps = rtop - rlow + 1;

    for (int idx = tid; idx < 65*33; idx += BNT) vw[idx] = 0.f;

    float4 f0 = (tid < 776) ? ldtile(rtop, tid) : make_float4(0,0,0,0);

    const int lane = tid & 31, w = tid >> 5;   // 32 warps

    for (int step = 0; step < nsteps; step++) {
        const int r = rtop - step;

        if (tid < 256) {
            int fi = tid*4, i = fi >> 5, j = fi & 31;
            float* p = &zt_s[i*33 + j];
            p[0]=f0.x; p[1]=f0.y; p[2]=f0.z; p[3]=f0.w;
        } else if (tid < 776) {
            reinterpret_cast<float4*>(gbuf)[tid - 256] = f0;
        }
        if (step + 1 < nsteps && tid < 776) f0 = ldtile(r-1, tid);
        __syncthreads();

        float ztr[NX];
        #pragma unroll
        for (int j = 0; j < NX; j++) ztr[j] = zt_s[lane*33 + j];

        for (int m = w; m < 65; m += 32) {
            float a0 = gbuf[m*NX + lane], a1 = 0.f;
            #pragma unroll
            for (int j = 0; j < NX; j += 2) {
                a0 -= vw[m*33 + j]     * ztr[j];
                a1 += vw[m*33 + j + 1] * ztr[j+1];
            }
            vw[m*33 + lane] = a0 - a1;
        }
        __syncthreads();

        if (r <= rmainTop) {
            float* orow = out + (size_t)r * 2048;
            #pragma unroll
            for (int t = 0; t < 2; t++) {
                const int idx = tid + BNT*t;
                const int m = idx >> 5, i = idx & 31;
                orow[idx] = vw[i] + vw[(m+1)*33 + i];
            }
        }
    }
}

extern "C" void kernel_launch(void* const* d_in, const int* in_sizes, int n_in,
                              void* d_out, int out_size) {
    const float* hess  = (const float*)d_in[0];   // (8192,32,32)
    const float* grads = (const float*)d_in[1];   // (8192,1,32)
    const float* Amat  = (const float*)d_in[2];   // (32,32)
    const float* Ptp   = (const float*)d_in[3];   // (32,32)
    const float* Pinit = (const float*)d_in[4];   // (32,32)
    const float* epsx  = (const float*)d_in[5];   // (8192,64,32)
    float* out = (float*)d_out;                   // (8192,64,32)
    (void)in_sizes; (void)n_in; (void)out_size;

    fwd_kernel<<<FW_BLOCKS, 128>>>(hess, grads, Amat, Ptp, Pinit);
    prep_kernel<<<RR, PNT>>>(epsx);
    bwd_kernel<<<BW_BLOCKS, BNT>>>(out);
}

// round 9
// speedup vs baseline: 3.7854x; 1.0640x over previous
#include <cuda_runtime.h>
#include <cstdint>

#define RR 8192
#define NX 32
#define FW_S 8
#define FW_W 20
#define NCHAIN (RR/FW_S)         // 1024 chains, one warp each
#define FWPB 4                   // warps per block
#define FW_BLOCKS (NCHAIN/FWPB)  // 256
#define BW_S 32
#define BW_W 20
#define BW_BLOCKS (RR/BW_S)      // 256
#define BNT 1024
#define PNT 256
#define FULLM 0xffffffffu

// forward products
__device__ float g_Uh [RR*NX*NX];  // [r][j][k] = Uhat[k][j] (valid k<=j; junk below)
__device__ float g_off[RR*NX*NX];  // [r][j][k] = off[j][k]  (row-major off)
__device__ float g_rs [RR*NX];     // rstd diag
__device__ float g_u  [RR*NX];
// prep products
__device__ float g_ZT [RR*NX*NX];  // [r][i][j] = Z[j][i], Z = off @ Linv
__device__ float g_G  [RR*65*NX];  // [r][m][i] = (g @ Linv)[m][i]

// ---------------------------------------------------------------------------
// Forward: one WARP per chain (warm-up 20). The 32x65 augmented system
// [M | -ap | w] lives column-per-lane in registers; Gaussian elimination via
// warp shuffles — zero block barriers. Per pivot the lane-local scaled pivot
// row (ak_s, bk_s = a[k]*invd, b[k]*invd) removes the per-update multiply.
// w eliminated in a post-pass using t_ik = Uhat[k][i]/d_k (local to lane i).
// pred-downdate fused into next step's build via per-warp smem copy of off.
// ---------------------------------------------------------------------------
__global__ __launch_bounds__(128) void fwd_kernel(
    const float* __restrict__ hess, const float* __restrict__ grads,
    const float* __restrict__ Amat, const float* __restrict__ Ptp,
    const float* __restrict__ Pinit)
{
    __shared__ __align__(16) float C1[NX*33];     // Ptp + apat   (columns: [i*33+j])
    __shared__ __align__(16) float C0[NX*33];     // Ptp          (last step, mfac=0)
    __shared__ __align__(16) float Ci[NX*33];     // Pinit + apat (r==0)
    __shared__ __align__(16) float nap[NX*33];    // -ap
    __shared__ __align__(16) float offp[FWPB][NX*36+4];  // per-warp offT, stride 36

    const int tid = threadIdx.x, lane = tid & 31, w = tid >> 5;

    // ---- block init: ap = A@Ptp, apat = ap@A^T, build C0/C1/Ci/nap ----
    {
        float* A_s = offp[0];          // temp (stride 33)
        float* P_s = offp[2];          // temp
        for (int idx = tid; idx < NX*NX; idx += 128) {
            int i = idx >> 5, j = idx & 31;
            A_s[i*33+j] = Amat[idx];
            P_s[i*33+j] = Ptp[idx];
        }
        __syncthreads();
        for (int idx = tid; idx < NX*NX; idx += 128) {  // nap = -(A@P)
            int i = idx >> 5, j = idx & 31;
            float s = 0.f;
            #pragma unroll
            for (int k = 0; k < NX; k++) s += A_s[i*33+k]*P_s[k*33+j];
            nap[i*33+j] = -s;
        }
        __syncthreads();
        for (int idx = tid; idx < NX*NX; idx += 128) {  // apat = ap@A^T; C's
            int i = idx >> 5, j = idx & 31;
            float s = 0.f;
            #pragma unroll
            for (int k = 0; k < NX; k++) s -= nap[i*33+k]*A_s[j*33+k];
            const float P = P_s[i*33+j];
            C1[i*33+j] = P + s;
            C0[i*33+j] = P;
            Ci[i*33+j] = Pinit[idx] + s;
        }
        __syncthreads();
    }

    const int chain = blockIdx.x*FWPB + w;
    const int rmain = chain*FW_S;
    int r0 = rmain - FW_W; if (r0 < 0) r0 = 0;
    const int nsteps = rmain + FW_S - r0;
    float* op = offp[w];

    float a[NX], b[NX], rsd[NX], offr[NX], hp[NX];
    float gv, wv, uacc = 0.f;

    #pragma unroll
    for (int k = 0; k < NX; k++) { offr[k] = 0.f; op[k*36+lane] = 0.f; }
    __syncwarp();

    #pragma unroll
    for (int i = 0; i < NX; i++) hp[i] = hess[(size_t)r0*1024 + i*32 + lane];
    gv = grads[r0*NX + lane];

    for (int step = 0; step < nsteps; step++) {
        const int r = r0 + step;
        const float* Cp = (r == 0) ? Ci : ((r == RR-1) ? C0 : C1);

        // ---- build: a = C + hess - off^T off   (col of M), b = -ap col ----
        #pragma unroll
        for (int i = 0; i < NX; i++) a[i] = Cp[i*33+lane] + hp[i];
        #pragma unroll
        for (int k = 0; k < NX; k++) {
            const float ok = offr[k];
            #pragma unroll
            for (int i4 = 0; i4 < NX; i4 += 4) {
                const float4 v = *(const float4*)&op[k*36 + i4];
                a[i4]   -= v.x*ok; a[i4+1] -= v.y*ok;
                a[i4+2] -= v.z*ok; a[i4+3] -= v.w*ok;
            }
        }
        #pragma unroll
        for (int i = 0; i < NX; i++) b[i] = nap[i*33+lane];
        wv = gv - uacc;   // w[lane] = grad[lane] - u . off[lane][:]

        if (step + 1 < nsteps) {   // prefetch next hess/grad under elimination
            #pragma unroll
            for (int i = 0; i < NX; i++) hp[i] = hess[(size_t)(r+1)*1024 + i*32 + lane];
            gv = grads[(r+1)*NX + lane];
        }

        // ---- shuffle elimination (no barriers, no per-update multiply) ----
        float dmine = 1.f;
        #pragma unroll
        for (int k = 0; k < NX; k++) {
            const float dk = __shfl_sync(FULLM, a[k], k);
            rsd[k] = dk;
            dmine = (lane == k) ? dk : dmine;
            const float invd = __frcp_rn(dk);
            const float ak_s = a[k]*invd;   // lane-local scaled pivot row entries
            const float bk_s = b[k]*invd;
            #pragma unroll
            for (int i = k+1; i < NX; i++) {
                const float t = __shfl_sync(FULLM, a[i], k);
                a[i] -= t*ak_s;
                b[i] -= t*bk_s;
            }
        }
        #pragma unroll
        for (int k = 0; k < NX; k++) rsd[k] = __frsqrt_rn(rsd[k]);
        const float rsmine = __frsqrt_rn(dmine);

        // ---- eliminate w: t_ik = Uhat[k][i]*invd_k = a[k]*rs_k^2 (local) ----
        #pragma unroll
        for (int k = 0; k < NX; k++) {
            const float wk = __shfl_sync(FULLM, wv, k);
            const float t = (lane > k) ? a[k]*rsd[k]*rsd[k] : 0.f;
            wv -= t*wk;
        }

        // ---- extraction: off row, u-dot for next w, smem offT ----
        uacc = 0.f;
        #pragma unroll
        for (int k = 0; k < NX; k++) {
            offr[k] = b[k]*rsd[k];
            const float uk = __shfl_sync(FULLM, wv, k) * rsd[k];
            uacc += uk*offr[k];
            op[k*36+lane] = offr[k];
        }
        __syncwarp();

        if (r >= rmain) {
            const size_t rb = (size_t)r*(NX*NX) + lane*NX;
            #pragma unroll
            for (int k4 = 0; k4 < NX; k4 += 4) {
                *(float4*)&g_off[rb+k4] = make_float4(offr[k4],offr[k4+1],offr[k4+2],offr[k4+3]);
                *(float4*)&g_Uh [rb+k4] = make_float4(a[k4],a[k4+1],a[k4+2],a[k4+3]);
            }
            g_rs[r*NX+lane] = rsmine;
            g_u [r*NX+lane] = wv * rsmine;
        }
    }
}

// ---------------------------------------------------------------------------
// prep: per-r parallel — rebuild L from raw Uhat + rs, invert it (32
// independent column substitutions), then ZT = (off@Linv)^T and G = g@Linv.
// L[i][k] = Uhat[k][i] * rs_k (true Cholesky factor), diag L[k][k] = 1/rs_k,
// and Linv diag = rs_k.
// ---------------------------------------------------------------------------
__global__ __launch_bounds__(PNT) void prep_kernel(const float* __restrict__ epsx)
{
    __shared__ float Lh_s[NX*33];     // Lh_s[k*33+i] = L[i][k] (i>k), diag rs_k
    __shared__ float linvT_s[NX*33];  // [j*33+i] = Linv[i][j]
    __shared__ float off_s[NX*33];    // [j*33+k] = off[j][k]
    __shared__ float g_sm[65*NX];
    __shared__ float rs_s[NX];

    const int tid = threadIdx.x;
    const int r = blockIdx.x;
    const size_t rb = (size_t)r * (NX*NX);

    if (tid < NX) rs_s[tid] = g_rs[r*NX + tid];
    {   // off rows
        float4 v = ((const float4*)(g_off + rb))[tid];
        int fi = tid*4, j = fi >> 5, k = fi & 31;
        float* p = &off_s[j*33 + k];
        p[0]=v.x; p[1]=v.y; p[2]=v.z; p[3]=v.w;
    }
    if (tid < NX) g_sm[tid] = g_u[r*NX + tid];
    {
        const float4* es = (const float4*)(epsx + (size_t)r*2048);
        float4* ed = (float4*)&g_sm[NX];
        ed[tid] = es[tid]; ed[tid+PNT] = es[tid+PNT];
    }
    for (int idx = tid; idx < NX*33; idx += PNT) linvT_s[idx] = 0.f;
    __syncthreads();   // rs_s ready

    {   // L[i][k] = Uh[i][k]*rs_k (k<i), rs_k (k==i), 0 else
        float4 v = ((const float4*)(g_Uh + rb))[tid];
        int fi = tid*4, i = fi >> 5, k = fi & 31;
        float vv[4] = {v.x, v.y, v.z, v.w};
        #pragma unroll
        for (int c = 0; c < 4; c++) {
            const int kk = k + c;
            const float rs = rs_s[kk];
            const float val = (kk < i) ? vv[c]*rs : ((kk == i) ? rs : 0.f);
            Lh_s[kk*33 + i] = val;
        }
    }
    __syncthreads();

    // invert L: lane j computes Linv column j (warp 0)
    if (tid < NX) {
        const int j = tid;
        linvT_s[j*33 + j] = Lh_s[j*33 + j];   // 1/L[j][j] = rs_j
        for (int i = 1; i < NX; i++) {
            if (j < i) {
                float s0 = 0.f, s1 = 0.f;
                int k = j;
                for (; k + 1 < i; k += 2) {
                    s0 += Lh_s[k*33 + i]     * linvT_s[j*33 + k];
                    s1 += Lh_s[(k+1)*33 + i] * linvT_s[j*33 + k + 1];
                }
                if (k < i) s0 += Lh_s[k*33 + i] * linvT_s[j*33 + k];
                linvT_s[j*33 + i] = -Lh_s[i*33 + i] * (s0 + s1);
            }
        }
    }
    __syncthreads();

    const int lane = tid & 31, w = tid >> 5;   // 8 warps
    for (int m = w; m < 65; m += 8) {          // G rows
        const float* grow = &g_sm[m*NX];
        float a0 = 0.f, a1 = 0.f;
        #pragma unroll
        for (int k = 0; k < NX; k += 2) {
            a0 += grow[k]   * linvT_s[lane*33 + k];
            a1 += grow[k+1] * linvT_s[lane*33 + k + 1];
        }
        g_G[(size_t)r*2080 + m*NX + lane] = a0 + a1;
    }
    for (int i = w; i < NX; i += 8) {          // ZT rows
        float a0 = 0.f, a1 = 0.f;
        #pragma unroll
        for (int k = 0; k < NX; k += 2) {
            a0 += off_s[lane*33 + k]     * linvT_s[i*33 + k];
            a1 += off_s[lane*33 + k + 1] * linvT_s[i*33 + k + 1];
        }
        g_ZT[rb + i*NX + lane] = a0 + a1;
    }
}

// ---------------------------------------------------------------------------
// Backward: chunked reverse scan (warm-up 20, chunk 32). ONE fused matmul
// per step: vw' = G' - vw @ Z
// ---------------------------------------------------------------------------
__device__ __forceinline__ float4 ldtile(int r, int idx) {
    if (idx < 256) return reinterpret_cast<const float4*>(g_ZT + (size_t)r*1024)[idx];
    return reinterpret_cast<const float4*>(g_G + (size_t)r*2080)[idx - 256];
}

__global__ __launch_bounds__(BNT) void bwd_kernel(float* __restrict__ out)
{
    __shared__ float vw[65*33];
    __shared__ float zt_s[NX*33];
    __shared__ __align__(16) float gbuf[65*NX];

    const int tid = threadIdx.x;
    const int b   = blockIdx.x;
    const int rlow     = b*BW_S;
    const int rmainTop = rlow + BW_S - 1;
    int rtop = rmainTop + BW_W; if (rtop > RR-1) rtop = RR-1;
    const int nsteps = rtop - rlow + 1;

    for (int idx = tid; idx < 65*33; idx += BNT) vw[idx] = 0.f;

    float4 f0 = (tid < 776) ? ldtile(rtop, tid) : make_float4(0,0,0,0);

    const int lane = tid & 31, w = tid >> 5;   // 32 warps

    for (int step = 0; step < nsteps; step++) {
        const int r = rtop - step;

        if (tid < 256) {
            int fi = tid*4, i = fi >> 5, j = fi & 31;
            float* p = &zt_s[i*33 + j];
            p[0]=f0.x; p[1]=f0.y; p[2]=f0.z; p[3]=f0.w;
        } else if (tid < 776) {
            reinterpret_cast<float4*>(gbuf)[tid - 256] = f0;
        }
        if (step + 1 < nsteps && tid < 776) f0 = ldtile(r-1, tid);
        __syncthreads();

        float ztr[NX];
        #pragma unroll
        for (int j = 0; j < NX; j++) ztr[j] = zt_s[lane*33 + j];

        for (int m = w; m < 65; m += 32) {
            float a0 = gbuf[m*NX + lane], a1 = 0.f;
            #pragma unroll
            for (int j = 0; j < NX; j += 2) {
                a0 -= vw[m*33 + j]     * ztr[j];
                a1 += vw[m*33 + j + 1] * ztr[j+1];
            }
            vw[m*33 + lane] = a0 - a1;
        }
        __syncthreads();

        if (r <= rmainTop) {
            float* orow = out + (size_t)r * 2048;
            const int idx = tid;
            const int m = idx >> 5, i = idx & 31;
            orow[idx] = vw[i] + vw[(m+1)*33 + i];
            const int idx2 = tid + BNT;
            const int m2 = idx2 >> 5, i2 = idx2 & 31;
            orow[idx2] = vw[i2] + vw[(m2+1)*33 + i2];
        }
    }
}

extern "C" void kernel_launch(void* const* d_in, const int* in_sizes, int n_in,
                              void* d_out, int out_size) {
    const float* hess  = (const float*)d_in[0];   // (8192,32,32)
    const float* grads = (const float*)d_in[1];   // (8192,1,32)
    const float* Amat  = (const float*)d_in[2];   // (32,32)
    const float* Ptp   = (const float*)d_in[3];   // (32,32)
    const float* Pinit = (const float*)d_in[4];   // (32,32)
    const float* epsx  = (const float*)d_in[5];   // (8192,64,32)
    float* out = (float*)d_out;                   // (8192,64,32)
    (void)in_sizes; (void)n_in; (void)out_size;

    fwd_kernel<<<FW_BLOCKS, 128>>>(hess, grads, Amat, Ptp, Pinit);
    prep_kernel<<<RR, PNT>>>(epsx);
    bwd_kernel<<<BW_BLOCKS, BNT>>>(out);
}